// round 5
// baseline (speedup 1.0000x reference)
#include <cuda_runtime.h>
#include <cuda_bf16.h>

#define N_VAR  100000
#define N_CSTR 50000
#define NEDGE  1000000
#define D      64
#define BN_EPS 1e-5f

typedef unsigned long long u64;

// ---------------- scratch ----------------
__device__ __nv_bfloat162 g_bf_node[N_VAR * 32];
__device__ __nv_bfloat162 g_bf_cstr[N_CSTR * 32];
__device__ float g_agg_node[N_VAR * D];
__device__ float g_agg_cstr[N_CSTR * D];
__device__ int2  g_e_node[NEDGE];
__device__ int2  g_e_cstr[NEDGE];
__device__ int   g_deg_node[N_VAR];
__device__ int   g_deg_cstr[N_CSTR];
__device__ int   g_row_node[N_VAR];
__device__ int   g_row_cstr[N_CSTR];
__device__ int   g_cur_node[N_VAR];
__device__ int   g_cur_cstr[N_CSTR];
__device__ float g_stats_node[2 * D];
__device__ float g_stats_cstr[2 * D];
__device__ float g_scale_node[D], g_shift_node[D];
__device__ float g_scale_cstr[D], g_shift_cstr[D];
__device__ int   g_bsum_node[32];
__device__ int   g_bsum_cstr[32];

// ---------------- helpers ----------------
__device__ __forceinline__ u64 fma2(u64 a, u64 b, u64 c) {
    u64 d;
    asm("fma.rn.f32x2 %0, %1, %2, %3;" : "=l"(d) : "l"(a), "l"(b), "l"(c));
    return d;
}
__device__ __forceinline__ float2 unpk(u64 v) {
    float2 f;
    asm("mov.b64 {%0,%1}, %2;" : "=f"(f.x), "=f"(f.y) : "l"(v));
    return f;
}

// ---------------- zero kernels ----------------
__global__ void k_zero_stats() {
    int i = threadIdx.x;
    if (i < 2 * D) { g_stats_node[i] = 0.f; g_stats_cstr[i] = 0.f; }
}
__global__ void k_zero_deg() {
    int i = blockIdx.x * blockDim.x + threadIdx.x;
    int stride = gridDim.x * blockDim.x;
    for (int j = i; j < N_VAR; j += stride) g_deg_node[j] = 0;
    for (int j = i; j < N_CSTR; j += stride) g_deg_cstr[j] = 0;
}

// ---------------- BN stats + bf16 conversion (R3-proven version) ----------------
__global__ void k_bnstats(const float* __restrict__ x, int n, int which) {
    float* stats = which ? g_stats_cstr : g_stats_node;
    __nv_bfloat16* bf = (__nv_bfloat16*)(which ? g_bf_cstr : g_bf_node);
    int c = threadIdx.x;                     // column 0..63
    int step = gridDim.x * blockDim.y;
    float s = 0.f, q = 0.f;
    for (int r = blockIdx.x * blockDim.y + threadIdx.y; r < n; r += step) {
        float v = x[(size_t)r * D + c];
        bf[(size_t)r * D + c] = __float2bfloat16_rn(v);
        s += v; q = fmaf(v, v, q);
    }
    __shared__ float shs[4][64], shq[4][64];
    shs[threadIdx.y][c] = s; shq[threadIdx.y][c] = q;
    __syncthreads();
    if (threadIdx.y == 0) {
        float S = shs[0][c] + shs[1][c] + shs[2][c] + shs[3][c];
        float Q = shq[0][c] + shq[1][c] + shq[2][c] + shq[3][c];
        atomicAdd(&stats[c], S);
        atomicAdd(&stats[D + c], Q);
    }
}

// ---------------- finalize BN scale/shift ----------------
__global__ void k_finstats(const float* __restrict__ gn, const float* __restrict__ bn,
                           const float* __restrict__ gc, const float* __restrict__ bc) {
    int c = threadIdx.x;
    if (c < D) {
        float m = g_stats_node[c] / (float)N_VAR;
        float v = g_stats_node[D + c] / (float)N_VAR - m * m;
        float sc = gn[c] * rsqrtf(v + BN_EPS);
        g_scale_node[c] = sc;
        g_shift_node[c] = fmaf(-m, sc, bn[c]);
    } else if (c < 2 * D) {
        int cc = c - D;
        float m = g_stats_cstr[cc] / (float)N_CSTR;
        float v = g_stats_cstr[D + cc] / (float)N_CSTR - m * m;
        float sc = gc[cc] * rsqrtf(v + BN_EPS);
        g_scale_cstr[cc] = sc;
        g_shift_cstr[cc] = fmaf(-m, sc, bc[cc]);
    }
}

// ---------------- degree histogram ----------------
__global__ void k_hist(const int* __restrict__ src, const int* __restrict__ dst) {
    for (int e = blockIdx.x * blockDim.x + threadIdx.x; e < NEDGE; e += gridDim.x * blockDim.x) {
        atomicAdd(&g_deg_node[dst[e]], 1);
        atomicAdd(&g_deg_cstr[src[e]], 1);
    }
}

// ---------------- scans ----------------
#define SCAN_T 256
#define SCAN_I 16
#define SCAN_CHUNK (SCAN_T * SCAN_I)
#define NB_NODE ((N_VAR + SCAN_CHUNK - 1) / SCAN_CHUNK)   // 25
#define NB_CSTR ((N_CSTR + SCAN_CHUNK - 1) / SCAN_CHUNK)  // 13

__global__ void k_scan1_all() {
    int side = (blockIdx.x >= NB_NODE);
    int blk  = side ? blockIdx.x - NB_NODE : blockIdx.x;
    const int* in = side ? g_deg_cstr : g_deg_node;
    int* out = side ? g_row_cstr : g_row_node;
    int* bsum = side ? g_bsum_cstr : g_bsum_node;
    int n = side ? N_CSTR : N_VAR;
    __shared__ int sh[SCAN_T];
    int t = threadIdx.x;
    int base = blk * SCAN_CHUNK + t * SCAN_I;
    int loc[SCAN_I];
    int s = 0;
#pragma unroll
    for (int i = 0; i < SCAN_I; i++) {
        int idx = base + i;
        int v = (idx < n) ? in[idx] : 0;
        loc[i] = s; s += v;
    }
    sh[t] = s;
    __syncthreads();
    for (int off = 1; off < SCAN_T; off <<= 1) {
        int v = (t >= off) ? sh[t - off] : 0;
        __syncthreads();
        sh[t] += v;
        __syncthreads();
    }
    int pre = (t > 0) ? sh[t - 1] : 0;
#pragma unroll
    for (int i = 0; i < SCAN_I; i++) {
        int idx = base + i;
        if (idx < n) out[idx] = pre + loc[i];
    }
    if (t == SCAN_T - 1) bsum[blk] = sh[t];
}

__global__ void k_scan2() {
    int t = threadIdx.x;
    if (t == 0) {
        int s = 0;
        for (int i = 0; i < NB_NODE; i++) { int v = g_bsum_node[i]; g_bsum_node[i] = s; s += v; }
    }
    if (t == 1) {
        int s = 0;
        for (int i = 0; i < NB_CSTR; i++) { int v = g_bsum_cstr[i]; g_bsum_cstr[i] = s; s += v; }
    }
}

__global__ void k_scan3_all() {
    int side = (blockIdx.x >= NB_NODE);
    int blk  = side ? blockIdx.x - NB_NODE : blockIdx.x;
    int* row = side ? g_row_cstr : g_row_node;
    int* cur = side ? g_cur_cstr : g_cur_node;
    const int* bsum = side ? g_bsum_cstr : g_bsum_node;
    int n = side ? N_CSTR : N_VAR;
    int add = bsum[blk];
    int base = blk * SCAN_CHUNK;
    for (int i = threadIdx.x; i < SCAN_CHUNK; i += SCAN_T) {
        int idx = base + i;
        if (idx < n) { int v = row[idx] + add; row[idx] = v; cur[idx] = v; }
    }
}

// ---------------- scatter edges into CSR slots ----------------
__global__ void k_scatter(const int* __restrict__ src, const int* __restrict__ dst,
                          const float* __restrict__ attr) {
    for (int e = blockIdx.x * blockDim.x + threadIdx.x; e < NEDGE; e += gridDim.x * blockDim.x) {
        int s = src[e], d = dst[e];
        int a = __float_as_int(attr[e]);
        int p = atomicAdd(&g_cur_node[d], 1);
        g_e_node[p] = make_int2(s, a);
        int q = atomicAdd(&g_cur_cstr[s], 1);
        g_e_cstr[q] = make_int2(d, a);
    }
}

// ---------------- gather: warp/node, batched edge loads + shfl broadcast ----------------
__global__ void k_gather_all() {
    int w = (blockIdx.x * blockDim.x + threadIdx.x) >> 5;
    int lane = threadIdx.x & 31;
    int side, node;
    if (w < N_VAR) { side = 0; node = w; }
    else { node = w - N_VAR; if (node >= N_CSTR) return; side = 1; }

    const int2* __restrict__ eb = side ? g_e_cstr : g_e_node;
    const int* __restrict__ row = side ? g_row_cstr : g_row_node;
    const int* __restrict__ deg = side ? g_deg_cstr : g_deg_node;
    const __nv_bfloat162* __restrict__ xs = side ? g_bf_node : g_bf_cstr;
    const float* __restrict__ sc = side ? g_scale_node : g_scale_cstr;  // SOURCE side affine
    const float* __restrict__ sf = side ? g_shift_node : g_shift_cstr;
    float* __restrict__ agg = side ? g_agg_cstr : g_agg_node;

    int beg = __ldg(&row[node]);
    int d = __ldg(&deg[node]);
    float2 acc = make_float2(0.f, 0.f);
    float sew = 0.f;

    for (int base = 0; base < d; base += 32) {
        int rem = d - base;
        int2 rec = make_int2(0, 0);
        if (lane < rem) rec = __ldg(&eb[beg + base + lane]);
        int m = min(rem, 32);
        for (int t = 0; t < m; t++) {
            int srcn = __shfl_sync(0xffffffffu, rec.x, t);
            float a = __int_as_float(__shfl_sync(0xffffffffu, rec.y, t));
            float2 xv = __bfloat1622float2(__ldg(&xs[(size_t)srcn * 32 + lane]));
            acc.x = fmaf(xv.x, a, acc.x);
            acc.y = fmaf(xv.y, a, acc.y);
            sew += a;
        }
    }
    float inv = 1.f / fmaxf((float)d, 1.f);
    float2 scl = ((const float2*)sc)[lane];
    float2 shf = ((const float2*)sf)[lane];
    float2 r;
    r.x = (scl.x * acc.x + shf.x * sew) * inv;
    r.y = (scl.y * acc.y + shf.y * sew) * inv;
    ((float2*)agg)[(size_t)node * 32 + lane] = r;
}
#define GATHER_BLOCKS (((N_VAR + N_CSTR) * 32 + 255) / 256)

// ---------------- dual 64x64 matvec + bias + residual + relu (both sides) ----------------
#define NOB_NODE ((N_VAR + 127) / 128)   // 782
#define NOB_CSTR ((N_CSTR + 127) / 128)  // 391
__global__ void __launch_bounds__(128) k_out_all(
        const float* __restrict__ nWrel, const float* __restrict__ nbrel,
        const float* __restrict__ nWroot, const float* __restrict__ nxraw,
        float* __restrict__ nout,
        const float* __restrict__ cWrel, const float* __restrict__ cbrel,
        const float* __restrict__ cWroot, const float* __restrict__ cxraw,
        float* __restrict__ cout) {
    int side = (blockIdx.x >= NOB_NODE);
    int blk  = side ? blockIdx.x - NOB_NODE : blockIdx.x;
    const float* Wrel  = side ? cWrel : nWrel;
    const float* brel  = side ? cbrel : nbrel;
    const float* Wroot = side ? cWroot : nWroot;
    const float* xraw  = side ? cxraw : nxraw;
    float* out = side ? cout : nout;
    const float* agg = side ? g_agg_cstr : g_agg_node;
    const float* sc = side ? g_scale_cstr : g_scale_node;
    const float* sf = side ? g_shift_cstr : g_shift_node;
    int n = side ? N_CSTR : N_VAR;

    __shared__ float sWrel[D * D];
    __shared__ float sWroot[D * D];
    __shared__ float sOut[4][32][17];
    __shared__ float sb[D];
    __shared__ u64 ssc[32], ssh[32];

    for (int i = threadIdx.x; i < D * D; i += blockDim.x) {
        sWrel[i] = Wrel[i];
        int j = i >> 6, k = i & 63;
        sWroot[i] = Wroot[i] + ((j == k) ? 1.f : 0.f);
    }
    if (threadIdx.x < D) sb[threadIdx.x] = brel[threadIdx.x];
    if (threadIdx.x < 32) {
        ssc[threadIdx.x] = ((const u64*)sc)[threadIdx.x];
        ssh[threadIdx.x] = ((const u64*)sf)[threadIdx.x];
    }
    __syncthreads();

    int v = blk * 128 + threadIdx.x;
    int vl = min(v, n - 1);

    u64 ap[32], xp[32];
    const ulonglong2* pa = (const ulonglong2*)(agg + (size_t)vl * D);
    const ulonglong2* px = (const ulonglong2*)(xraw + (size_t)vl * D);
#pragma unroll
    for (int i = 0; i < 16; i++) {
        ulonglong2 t = pa[i]; ap[2 * i] = t.x; ap[2 * i + 1] = t.y;
        t = px[i];
        xp[2 * i]     = fma2(t.x, ssc[2 * i],     ssh[2 * i]);
        xp[2 * i + 1] = fma2(t.y, ssc[2 * i + 1], ssh[2 * i + 1]);
    }

    int w = threadIdx.x >> 5, lane = threadIdx.x & 31;
    int v0w = blk * 128 + w * 32;

    for (int jt = 0; jt < D; jt += 16) {
        for (int jj = 0; jj < 16; jj++) {
            int j = jt + jj;
            const ulonglong2* wr = (const ulonglong2*)(sWrel + j * D);
            const ulonglong2* wo = (const ulonglong2*)(sWroot + j * D);
            u64 a0 = 0, a1 = 0, b0 = 0, b1 = 0;
#pragma unroll
            for (int kk = 0; kk < 16; kk++) {
                ulonglong2 w1 = wr[kk];
                ulonglong2 w2 = wo[kk];
                a0 = fma2(ap[2 * kk],     w1.x, a0);
                a1 = fma2(ap[2 * kk + 1], w1.y, a1);
                b0 = fma2(xp[2 * kk],     w2.x, b0);
                b1 = fma2(xp[2 * kk + 1], w2.y, b1);
            }
            float2 fa0 = unpk(a0), fa1 = unpk(a1), fb0 = unpk(b0), fb1 = unpk(b1);
            float r = ((fa0.x + fa0.y) + (fa1.x + fa1.y)) +
                      ((fb0.x + fb0.y) + (fb1.x + fb1.y)) + sb[j];
            sOut[w][lane][jj] = fmaxf(r, 0.f);
        }
        __syncwarp();
        int col = lane & 15, rh = lane >> 4;
        for (int r2 = 0; r2 < 32; r2 += 2) {
            int rrow = r2 + rh;
            int node = v0w + rrow;
            if (node < n) out[(size_t)node * D + jt + col] = sOut[w][rrow][col];
        }
        __syncwarp();
    }
}

// ---------------- launch ----------------
extern "C" void kernel_launch(void* const* d_in, const int* in_sizes, int n_in,
                              void* d_out, int out_size) {
    (void)in_sizes; (void)n_in; (void)out_size;
    const float* var_feats   = (const float*)d_in[0];
    const float* cstr_feats  = (const float*)d_in[1];
    const int*   edge_src    = (const int*)d_in[2];
    const int*   edge_dst    = (const int*)d_in[3];
    const float* edge_attr   = (const float*)d_in[4];
    const float* gn          = (const float*)d_in[5];
    const float* bn          = (const float*)d_in[6];
    const float* gc          = (const float*)d_in[7];
    const float* bc          = (const float*)d_in[8];
    const float* node_rel_w  = (const float*)d_in[9];
    const float* node_rel_b  = (const float*)d_in[10];
    const float* node_root_w = (const float*)d_in[11];
    const float* cstr_rel_w  = (const float*)d_in[12];
    const float* cstr_rel_b  = (const float*)d_in[13];
    const float* cstr_root_w = (const float*)d_in[14];

    float* out_node = (float*)d_out;
    float* out_cstr = out_node + (size_t)N_VAR * D;

    // idx 0-2
    k_zero_stats<<<1, 128>>>();
    k_bnstats<<<296, dim3(64, 4)>>>(var_feats, N_VAR, 0);
    k_bnstats<<<296, dim3(64, 4)>>>(cstr_feats, N_CSTR, 1);
    // idx 3: PROFILING PROBE — duplicate k_out_all. In steady-state graph
    // replays g_agg/g_scale hold last replay's identical values, so this
    // measures the real k_out. The true k_out at the end overwrites every
    // output element, so correctness is unaffected (first call included).
    k_out_all<<<NOB_NODE + NOB_CSTR, 128>>>(
        node_rel_w, node_rel_b, node_root_w, var_feats, out_node,
        cstr_rel_w, cstr_rel_b, cstr_root_w, cstr_feats, out_cstr);
    // idx 4+: real pipeline
    k_finstats<<<1, 128>>>(gn, bn, gc, bc);
    k_zero_deg<<<391, 256>>>();
    k_hist<<<2048, 256>>>(edge_src, edge_dst);
    k_scan1_all<<<NB_NODE + NB_CSTR, SCAN_T>>>();
    k_scan2<<<1, 2>>>();
    k_scan3_all<<<NB_NODE + NB_CSTR, SCAN_T>>>();
    k_scatter<<<2048, 256>>>(edge_src, edge_dst, edge_attr);
    k_gather_all<<<GATHER_BLOCKS, 256>>>();
    k_out_all<<<NOB_NODE + NOB_CSTR, 128>>>(
        node_rel_w, node_rel_b, node_root_w, var_feats, out_node,
        cstr_rel_w, cstr_rel_b, cstr_root_w, cstr_feats, out_cstr);
}

// round 6
// speedup vs baseline: 1.5111x; 1.5111x over previous
#include <cuda_runtime.h>
#include <cuda_bf16.h>

#define N_VAR  100000
#define N_CSTR 50000
#define NEDGE  1000000
#define D      64
#define BN_EPS 1e-5f

typedef unsigned long long u64;

// ---------------- scratch ----------------
__device__ __nv_bfloat162 g_bf_node[N_VAR * 32];
__device__ __nv_bfloat162 g_bf_cstr[N_CSTR * 32];
__device__ float g_agg_node[N_VAR * D];
__device__ float g_agg_cstr[N_CSTR * D];
__device__ int2  g_e_node[NEDGE];
__device__ int2  g_e_cstr[NEDGE];
__device__ int   g_deg_node[N_VAR];
__device__ int   g_deg_cstr[N_CSTR];
__device__ int   g_row_node[N_VAR];
__device__ int   g_row_cstr[N_CSTR];
__device__ int   g_cur_node[N_VAR];
__device__ int   g_cur_cstr[N_CSTR];
__device__ float g_stats_node[2 * D];
__device__ float g_stats_cstr[2 * D];
__device__ float g_scale_node[D], g_shift_node[D];
__device__ float g_scale_cstr[D], g_shift_cstr[D];
__device__ int   g_bsum_node[32];
__device__ int   g_bsum_cstr[32];

// ---------------- helpers ----------------
__device__ __forceinline__ u64 fma2(u64 a, u64 b, u64 c) {
    u64 d;
    asm("fma.rn.f32x2 %0, %1, %2, %3;" : "=l"(d) : "l"(a), "l"(b), "l"(c));
    return d;
}
__device__ __forceinline__ float2 unpk(u64 v) {
    float2 f;
    asm("mov.b64 {%0,%1}, %2;" : "=f"(f.x), "=f"(f.y) : "l"(v));
    return f;
}
__device__ __forceinline__ u64 dup2(float x) {
    u64 r;
    asm("mov.b64 %0, {%1, %1};" : "=l"(r) : "f"(x));
    return r;
}

// ---------------- zero kernels ----------------
__global__ void k_zero_deg() {
    int i = blockIdx.x * blockDim.x + threadIdx.x;
    int stride = gridDim.x * blockDim.x;
    for (int j = i; j < N_VAR; j += stride) g_deg_node[j] = 0;
    for (int j = i; j < N_CSTR; j += stride) g_deg_cstr[j] = 0;
}
__global__ void k_zero_stats() {
    int i = threadIdx.x;
    if (i < 2 * D) { g_stats_node[i] = 0.f; g_stats_cstr[i] = 0.f; }
}

// ---------------- BN stats + bf16 conversion ----------------
__global__ void k_bnstats(const float* __restrict__ x, int n, int which) {
    float* stats = which ? g_stats_cstr : g_stats_node;
    __nv_bfloat16* bf = (__nv_bfloat16*)(which ? g_bf_cstr : g_bf_node);
    int c = threadIdx.x;
    int step = gridDim.x * blockDim.y;
    float s = 0.f, q = 0.f;
    for (int r = blockIdx.x * blockDim.y + threadIdx.y; r < n; r += step) {
        float v = x[(size_t)r * D + c];
        bf[(size_t)r * D + c] = __float2bfloat16_rn(v);
        s += v; q = fmaf(v, v, q);
    }
    __shared__ float shs[4][64], shq[4][64];
    shs[threadIdx.y][c] = s; shq[threadIdx.y][c] = q;
    __syncthreads();
    if (threadIdx.y == 0) {
        float S = shs[0][c] + shs[1][c] + shs[2][c] + shs[3][c];
        float Q = shq[0][c] + shq[1][c] + shq[2][c] + shq[3][c];
        atomicAdd(&stats[c], S);
        atomicAdd(&stats[D + c], Q);
    }
}

// ---------------- finalize BN scale/shift ----------------
__global__ void k_finstats(const float* __restrict__ gn, const float* __restrict__ bn,
                           const float* __restrict__ gc, const float* __restrict__ bc) {
    int c = threadIdx.x;
    if (c < D) {
        float m = g_stats_node[c] / (float)N_VAR;
        float v = g_stats_node[D + c] / (float)N_VAR - m * m;
        float sc = gn[c] * rsqrtf(v + BN_EPS);
        g_scale_node[c] = sc;
        g_shift_node[c] = fmaf(-m, sc, bn[c]);
    } else if (c < 2 * D) {
        int cc = c - D;
        float m = g_stats_cstr[cc] / (float)N_CSTR;
        float v = g_stats_cstr[D + cc] / (float)N_CSTR - m * m;
        float sc = gc[cc] * rsqrtf(v + BN_EPS);
        g_scale_cstr[cc] = sc;
        g_shift_cstr[cc] = fmaf(-m, sc, bc[cc]);
    }
}

// ---------------- degree histogram ----------------
__global__ void k_hist(const int* __restrict__ src, const int* __restrict__ dst) {
    for (int e = blockIdx.x * blockDim.x + threadIdx.x; e < NEDGE; e += gridDim.x * blockDim.x) {
        atomicAdd(&g_deg_node[dst[e]], 1);
        atomicAdd(&g_deg_cstr[src[e]], 1);
    }
}

// ---------------- scans ----------------
#define SCAN_T 256
#define SCAN_I 16
#define SCAN_CHUNK (SCAN_T * SCAN_I)
#define NB_NODE ((N_VAR + SCAN_CHUNK - 1) / SCAN_CHUNK)   // 25
#define NB_CSTR ((N_CSTR + SCAN_CHUNK - 1) / SCAN_CHUNK)  // 13

__global__ void k_scan1_all() {
    int side = (blockIdx.x >= NB_NODE);
    int blk  = side ? blockIdx.x - NB_NODE : blockIdx.x;
    const int* in = side ? g_deg_cstr : g_deg_node;
    int* out = side ? g_row_cstr : g_row_node;
    int* bsum = side ? g_bsum_cstr : g_bsum_node;
    int n = side ? N_CSTR : N_VAR;
    __shared__ int sh[SCAN_T];
    int t = threadIdx.x;
    int base = blk * SCAN_CHUNK + t * SCAN_I;
    int loc[SCAN_I];
    int s = 0;
#pragma unroll
    for (int i = 0; i < SCAN_I; i++) {
        int idx = base + i;
        int v = (idx < n) ? in[idx] : 0;
        loc[i] = s; s += v;
    }
    sh[t] = s;
    __syncthreads();
    for (int off = 1; off < SCAN_T; off <<= 1) {
        int v = (t >= off) ? sh[t - off] : 0;
        __syncthreads();
        sh[t] += v;
        __syncthreads();
    }
    int pre = (t > 0) ? sh[t - 1] : 0;
#pragma unroll
    for (int i = 0; i < SCAN_I; i++) {
        int idx = base + i;
        if (idx < n) out[idx] = pre + loc[i];
    }
    if (t == SCAN_T - 1) bsum[blk] = sh[t];
}

__global__ void k_scan2() {
    int t = threadIdx.x;
    if (t == 0) {
        int s = 0;
        for (int i = 0; i < NB_NODE; i++) { int v = g_bsum_node[i]; g_bsum_node[i] = s; s += v; }
    }
    if (t == 1) {
        int s = 0;
        for (int i = 0; i < NB_CSTR; i++) { int v = g_bsum_cstr[i]; g_bsum_cstr[i] = s; s += v; }
    }
}

__global__ void k_scan3_all() {
    int side = (blockIdx.x >= NB_NODE);
    int blk  = side ? blockIdx.x - NB_NODE : blockIdx.x;
    int* row = side ? g_row_cstr : g_row_node;
    int* cur = side ? g_cur_cstr : g_cur_node;
    const int* bsum = side ? g_bsum_cstr : g_bsum_node;
    int n = side ? N_CSTR : N_VAR;
    int add = bsum[blk];
    int base = blk * SCAN_CHUNK;
    for (int i = threadIdx.x; i < SCAN_CHUNK; i += SCAN_T) {
        int idx = base + i;
        if (idx < n) { int v = row[idx] + add; row[idx] = v; cur[idx] = v; }
    }
}

// ---------------- scatter edges into CSR slots ----------------
__global__ void k_scatter(const int* __restrict__ src, const int* __restrict__ dst,
                          const float* __restrict__ attr) {
    for (int e = blockIdx.x * blockDim.x + threadIdx.x; e < NEDGE; e += gridDim.x * blockDim.x) {
        int s = src[e], d = dst[e];
        int a = __float_as_int(attr[e]);
        int p = atomicAdd(&g_cur_node[d], 1);
        g_e_node[p] = make_int2(s, a);
        int q = atomicAdd(&g_cur_cstr[s], 1);
        g_e_cstr[q] = make_int2(d, a);
    }
}

// ---------------- gather: warp/node, batched edge loads + shfl broadcast ----------------
__global__ void k_gather_all() {
    int w = (blockIdx.x * blockDim.x + threadIdx.x) >> 5;
    int lane = threadIdx.x & 31;
    int side, node;
    if (w < N_VAR) { side = 0; node = w; }
    else { node = w - N_VAR; if (node >= N_CSTR) return; side = 1; }

    const int2* __restrict__ eb = side ? g_e_cstr : g_e_node;
    const int* __restrict__ row = side ? g_row_cstr : g_row_node;
    const int* __restrict__ deg = side ? g_deg_cstr : g_deg_node;
    const __nv_bfloat162* __restrict__ xs = side ? g_bf_node : g_bf_cstr;
    const float* __restrict__ sc = side ? g_scale_node : g_scale_cstr;
    const float* __restrict__ sf = side ? g_shift_node : g_shift_cstr;
    float* __restrict__ agg = side ? g_agg_cstr : g_agg_node;

    int beg = __ldg(&row[node]);
    int d = __ldg(&deg[node]);
    float2 acc = make_float2(0.f, 0.f);
    float sew = 0.f;

    for (int base = 0; base < d; base += 32) {
        int rem = d - base;
        int2 rec = make_int2(0, 0);
        if (lane < rem) rec = __ldg(&eb[beg + base + lane]);
        int m = min(rem, 32);
        for (int t = 0; t < m; t++) {
            int srcn = __shfl_sync(0xffffffffu, rec.x, t);
            float a = __int_as_float(__shfl_sync(0xffffffffu, rec.y, t));
            float2 xv = __bfloat1622float2(__ldg(&xs[(size_t)srcn * 32 + lane]));
            acc.x = fmaf(xv.x, a, acc.x);
            acc.y = fmaf(xv.y, a, acc.y);
            sew += a;
        }
    }
    float inv = 1.f / fmaxf((float)d, 1.f);
    float2 scl = ((const float2*)sc)[lane];
    float2 shf = ((const float2*)sf)[lane];
    float2 r;
    r.x = (scl.x * acc.x + shf.x * sew) * inv;
    r.y = (scl.y * acc.y + shf.y * sew) * inv;
    ((float2*)agg)[(size_t)node * 32 + lane] = r;
}
#define GATHER_BLOCKS (((N_VAR + N_CSTR) * 32 + 255) / 256)

// ---------------- output: register-blocked fused GEMM ----------------
// C[150k x 64] = relu( [agg | scale*xraw+shift] (K=128) @ [Wrel^T ; Wroot^T + I] + b )
// Block: 128 rows x 64 cols, 256 threads, micro-tile 8x4 (row-pairs packed f32x2).
#define NOB_NODE ((N_VAR + 127) / 128)   // 782
#define NOB_CSTR ((N_CSTR + 127) / 128)  // 391
__global__ void __launch_bounds__(256) k_out_gemm(
        const float* __restrict__ nWrel, const float* __restrict__ nbrel,
        const float* __restrict__ nWroot, const float* __restrict__ nxraw,
        float* __restrict__ nout,
        const float* __restrict__ cWrel, const float* __restrict__ cbrel,
        const float* __restrict__ cWroot, const float* __restrict__ cxraw,
        float* __restrict__ cout) {
    int side = (blockIdx.x >= NOB_NODE);
    int blk  = side ? blockIdx.x - NOB_NODE : blockIdx.x;
    const float* __restrict__ Wrel  = side ? cWrel : nWrel;
    const float* __restrict__ brel  = side ? cbrel : nbrel;
    const float* __restrict__ Wroot = side ? cWroot : nWroot;
    const float* __restrict__ xr    = side ? cxraw : nxraw;
    float* __restrict__ out = side ? cout : nout;
    const float* __restrict__ agg = side ? g_agg_cstr : g_agg_node;
    const float* __restrict__ sc = side ? g_scale_cstr : g_scale_node;
    const float* __restrict__ sf = side ? g_shift_cstr : g_shift_node;
    int n = side ? N_CSTR : N_VAR;

    __shared__ float sW[128][68];     // k-major: sW[k][j]
    __shared__ float sA[16][132];     // k-major chunk: sA[k][m]
    __shared__ float4 sScale[16], sShift[16];

    int tid = threadIdx.x;
    int tx = tid & 15, ty = tid >> 4;

    // W: sW[k][j] = Wrel[j][k]; sW[64+k][j] = Wroot[j][k] + (j==k)
    for (int i = tid; i < D * D; i += 256) {
        int j = i >> 6, k = i & 63;
        sW[k][j] = Wrel[i];
        sW[64 + k][j] = Wroot[i] + ((j == k) ? 1.f : 0.f);
    }
    if (tid < 16) {
        sScale[tid] = ((const float4*)sc)[tid];
        sShift[tid] = ((const float4*)sf)[tid];
    }

    int base = blk * 128;
    int idx0 = tid, idx1 = tid + 256;
    int m0 = idx0 >> 2, q0 = idx0 & 3;
    int m1 = idx1 >> 2, q1 = idx1 & 3;
    int r0 = min(base + m0, n - 1);
    int r1 = min(base + m1, n - 1);

    // bias-initialized packed accumulators: acc[rowpair][col]
    float4 bv = *(const float4*)(brel + tx * 4);
    u64 bb0 = dup2(bv.x), bb1 = dup2(bv.y), bb2 = dup2(bv.z), bb3 = dup2(bv.w);
    u64 acc[4][4];
#pragma unroll
    for (int rp = 0; rp < 4; rp++) {
        acc[rp][0] = bb0; acc[rp][1] = bb1; acc[rp][2] = bb2; acc[rp][3] = bb3;
    }

    float4 p0, p1;
    // chunk load into registers (c<4: agg, c>=4: affine(xraw))
    auto loadc = [&](int c, float4& a, float4& b2) {
        const float* src = (c < 4) ? agg : xr;
        int coff = (c & 3) << 4;
        a  = __ldg((const float4*)(src + (size_t)r0 * D + coff + q0 * 4));
        b2 = __ldg((const float4*)(src + (size_t)r1 * D + coff + q1 * 4));
        if (c >= 4) {
            float4 s0 = sScale[(c & 3) * 4 + q0], h0 = sShift[(c & 3) * 4 + q0];
            float4 s1 = sScale[(c & 3) * 4 + q1], h1 = sShift[(c & 3) * 4 + q1];
            a.x = fmaf(a.x, s0.x, h0.x); a.y = fmaf(a.y, s0.y, h0.y);
            a.z = fmaf(a.z, s0.z, h0.z); a.w = fmaf(a.w, s0.w, h0.w);
            b2.x = fmaf(b2.x, s1.x, h1.x); b2.y = fmaf(b2.y, s1.y, h1.y);
            b2.z = fmaf(b2.z, s1.z, h1.z); b2.w = fmaf(b2.w, s1.w, h1.w);
        }
    };
    auto storec = [&](const float4& a, const float4& b2) {
        int k0 = q0 * 4;
        sA[k0 + 0][m0] = a.x; sA[k0 + 1][m0] = a.y; sA[k0 + 2][m0] = a.z; sA[k0 + 3][m0] = a.w;
        int k1 = q1 * 4;
        sA[k1 + 0][m1] = b2.x; sA[k1 + 1][m1] = b2.y; sA[k1 + 2][m1] = b2.z; sA[k1 + 3][m1] = b2.w;
    };

    loadc(0, p0, p1);
    __syncthreads();           // sW/scales ready; nobody computing yet
    storec(p0, p1);
    __syncthreads();

    for (int c = 0; c < 8; c++) {
        if (c < 7) loadc(c + 1, p0, p1);   // prefetch overlaps compute
        int kb = c << 4;
#pragma unroll
        for (int kk = 0; kk < 16; kk++) {
            ulonglong2 A0 = *(const ulonglong2*)&sA[kk][ty * 8];
            ulonglong2 A1 = *(const ulonglong2*)&sA[kk][ty * 8 + 4];
            float4 b = *(const float4*)&sW[kb + kk][tx * 4];
            u64 b0 = dup2(b.x), b1 = dup2(b.y), b2 = dup2(b.z), b3 = dup2(b.w);
            acc[0][0] = fma2(A0.x, b0, acc[0][0]);
            acc[0][1] = fma2(A0.x, b1, acc[0][1]);
            acc[0][2] = fma2(A0.x, b2, acc[0][2]);
            acc[0][3] = fma2(A0.x, b3, acc[0][3]);
            acc[1][0] = fma2(A0.y, b0, acc[1][0]);
            acc[1][1] = fma2(A0.y, b1, acc[1][1]);
            acc[1][2] = fma2(A0.y, b2, acc[1][2]);
            acc[1][3] = fma2(A0.y, b3, acc[1][3]);
            acc[2][0] = fma2(A1.x, b0, acc[2][0]);
            acc[2][1] = fma2(A1.x, b1, acc[2][1]);
            acc[2][2] = fma2(A1.x, b2, acc[2][2]);
            acc[2][3] = fma2(A1.x, b3, acc[2][3]);
            acc[3][0] = fma2(A1.y, b0, acc[3][0]);
            acc[3][1] = fma2(A1.y, b1, acc[3][1]);
            acc[3][2] = fma2(A1.y, b2, acc[3][2]);
            acc[3][3] = fma2(A1.y, b3, acc[3][3]);
        }
        if (c < 7) {
            __syncthreads();   // all done reading sA chunk c
            storec(p0, p1);
            __syncthreads();   // chunk c+1 visible
        }
    }

    // epilogue: relu + coalesced float4 stores (row-pair unpack)
#pragma unroll
    for (int rp = 0; rp < 4; rp++) {
        float2 c0 = unpk(acc[rp][0]), c1 = unpk(acc[rp][1]);
        float2 c2 = unpk(acc[rp][2]), c3 = unpk(acc[rp][3]);
        int row = base + ty * 8 + rp * 2;
        if (row < n) {
            float4 v = make_float4(fmaxf(c0.x, 0.f), fmaxf(c1.x, 0.f),
                                   fmaxf(c2.x, 0.f), fmaxf(c3.x, 0.f));
            *(float4*)(out + (size_t)row * D + tx * 4) = v;
        }
        if (row + 1 < n) {
            float4 v = make_float4(fmaxf(c0.y, 0.f), fmaxf(c1.y, 0.f),
                                   fmaxf(c2.y, 0.f), fmaxf(c3.y, 0.f));
            *(float4*)(out + (size_t)(row + 1) * D + tx * 4) = v;
        }
    }
}

// ---------------- launch ----------------
extern "C" void kernel_launch(void* const* d_in, const int* in_sizes, int n_in,
                              void* d_out, int out_size) {
    (void)in_sizes; (void)n_in; (void)out_size;
    const float* var_feats   = (const float*)d_in[0];
    const float* cstr_feats  = (const float*)d_in[1];
    const int*   edge_src    = (const int*)d_in[2];
    const int*   edge_dst    = (const int*)d_in[3];
    const float* edge_attr   = (const float*)d_in[4];
    const float* gn          = (const float*)d_in[5];
    const float* bn          = (const float*)d_in[6];
    const float* gc          = (const float*)d_in[7];
    const float* bc          = (const float*)d_in[8];
    const float* node_rel_w  = (const float*)d_in[9];
    const float* node_rel_b  = (const float*)d_in[10];
    const float* node_root_w = (const float*)d_in[11];
    const float* cstr_rel_w  = (const float*)d_in[12];
    const float* cstr_rel_b  = (const float*)d_in[13];
    const float* cstr_root_w = (const float*)d_in[14];

    float* out_node = (float*)d_out;
    float* out_cstr = out_node + (size_t)N_VAR * D;

    // launch order chosen so the 4th launch (ncu's captured slot) is k_hist
    k_zero_deg<<<391, 256>>>();
    k_zero_stats<<<1, 128>>>();
    k_bnstats<<<296, dim3(64, 4)>>>(var_feats, N_VAR, 0);
    k_hist<<<2048, 256>>>(edge_src, edge_dst);                    // <- profiled
    k_bnstats<<<296, dim3(64, 4)>>>(cstr_feats, N_CSTR, 1);
    k_finstats<<<1, 128>>>(gn, bn, gc, bc);
    k_scan1_all<<<NB_NODE + NB_CSTR, SCAN_T>>>();
    k_scan2<<<1, 2>>>();
    k_scan3_all<<<NB_NODE + NB_CSTR, SCAN_T>>>();
    k_scatter<<<2048, 256>>>(edge_src, edge_dst, edge_attr);
    k_gather_all<<<GATHER_BLOCKS, 256>>>();
    k_out_gemm<<<NOB_NODE + NOB_CSTR, 256>>>(
        node_rel_w, node_rel_b, node_root_w, var_feats, out_node,
        cstr_rel_w, cstr_rel_b, cstr_root_w, cstr_feats, out_cstr);
}

// round 8
// speedup vs baseline: 1.7613x; 1.1656x over previous
#include <cuda_runtime.h>
#include <cuda_bf16.h>

#define N_VAR  100000
#define N_CSTR 50000
#define NEDGE  1000000
#define D      64
#define BN_EPS 1e-5f

typedef unsigned long long u64;
typedef unsigned int u32;

// ---------------- scratch ----------------
__device__ __nv_bfloat162 g_bf_node[N_VAR * 32];
__device__ __nv_bfloat162 g_bf_cstr[N_CSTR * 32];
__device__ __nv_bfloat162 g_agg_node[N_VAR * 32];   // mean-aggregated messages, bf16
__device__ __nv_bfloat162 g_agg_cstr[N_CSTR * 32];
__device__ int2  g_e_node[NEDGE];
__device__ int2  g_e_cstr[NEDGE];
__device__ int   g_deg_node[N_VAR];
__device__ int   g_deg_cstr[N_CSTR];
__device__ int   g_row_node[N_VAR];
__device__ int   g_row_cstr[N_CSTR];
__device__ int   g_cur_node[N_VAR];
__device__ int   g_cur_cstr[N_CSTR];
__device__ float g_stats_node[2 * D];
__device__ float g_stats_cstr[2 * D];
__device__ float g_scale_node[D], g_shift_node[D];
__device__ float g_scale_cstr[D], g_shift_cstr[D];
__device__ int   g_bsum_node[32];
__device__ int   g_bsum_cstr[32];

// ---------------- helpers ----------------
__device__ __forceinline__ u32 pk2(float lo, float hi) {
    u32 r;
    asm("cvt.rn.bf16x2.f32 %0, %1, %2;" : "=r"(r) : "f"(hi), "f"(lo));
    return r;
}
__device__ __forceinline__ void hmma16816(float& d0, float& d1, float& d2, float& d3,
                                          u32 a0, u32 a1, u32 a2, u32 a3,
                                          u32 b0, u32 b1) {
    asm volatile(
        "mma.sync.aligned.m16n8k16.row.col.f32.bf16.bf16.f32 "
        "{%0,%1,%2,%3}, {%4,%5,%6,%7}, {%8,%9}, {%0,%1,%2,%3};"
        : "+f"(d0), "+f"(d1), "+f"(d2), "+f"(d3)
        : "r"(a0), "r"(a1), "r"(a2), "r"(a3), "r"(b0), "r"(b1));
}

// ---------------- zero kernels ----------------
__global__ void k_zero_deg() {
    int i = blockIdx.x * blockDim.x + threadIdx.x;
    int stride = gridDim.x * blockDim.x;
    for (int j = i; j < N_VAR; j += stride) g_deg_node[j] = 0;
    for (int j = i; j < N_CSTR; j += stride) g_deg_cstr[j] = 0;
}
__global__ void k_zero_stats() {
    int i = threadIdx.x;
    if (i < 2 * D) { g_stats_node[i] = 0.f; g_stats_cstr[i] = 0.f; }
}

// ---------------- BN stats + bf16 conversion ----------------
__global__ void k_bnstats(const float* __restrict__ x, int n, int which) {
    float* stats = which ? g_stats_cstr : g_stats_node;
    __nv_bfloat16* bf = (__nv_bfloat16*)(which ? g_bf_cstr : g_bf_node);
    int c = threadIdx.x;
    int step = gridDim.x * blockDim.y;
    float s = 0.f, q = 0.f;
    for (int r = blockIdx.x * blockDim.y + threadIdx.y; r < n; r += step) {
        float v = x[(size_t)r * D + c];
        bf[(size_t)r * D + c] = __float2bfloat16_rn(v);
        s += v; q = fmaf(v, v, q);
    }
    __shared__ float shs[4][64], shq[4][64];
    shs[threadIdx.y][c] = s; shq[threadIdx.y][c] = q;
    __syncthreads();
    if (threadIdx.y == 0) {
        float S = shs[0][c] + shs[1][c] + shs[2][c] + shs[3][c];
        float Q = shq[0][c] + shq[1][c] + shq[2][c] + shq[3][c];
        atomicAdd(&stats[c], S);
        atomicAdd(&stats[D + c], Q);
    }
}

// ---------------- finalize BN scale/shift ----------------
__global__ void k_finstats(const float* __restrict__ gn, const float* __restrict__ bn,
                           const float* __restrict__ gc, const float* __restrict__ bc) {
    int c = threadIdx.x;
    if (c < D) {
        float m = g_stats_node[c] / (float)N_VAR;
        float v = g_stats_node[D + c] / (float)N_VAR - m * m;
        float sc = gn[c] * rsqrtf(v + BN_EPS);
        g_scale_node[c] = sc;
        g_shift_node[c] = fmaf(-m, sc, bn[c]);
    } else if (c < 2 * D) {
        int cc = c - D;
        float m = g_stats_cstr[cc] / (float)N_CSTR;
        float v = g_stats_cstr[D + cc] / (float)N_CSTR - m * m;
        float sc = gc[cc] * rsqrtf(v + BN_EPS);
        g_scale_cstr[cc] = sc;
        g_shift_cstr[cc] = fmaf(-m, sc, bc[cc]);
    }
}

// ---------------- degree histogram ----------------
__global__ void k_hist(const int* __restrict__ src, const int* __restrict__ dst) {
    for (int e = blockIdx.x * blockDim.x + threadIdx.x; e < NEDGE; e += gridDim.x * blockDim.x) {
        atomicAdd(&g_deg_node[dst[e]], 1);
        atomicAdd(&g_deg_cstr[src[e]], 1);
    }
}

// ---------------- scans ----------------
#define SCAN_T 256
#define SCAN_I 16
#define SCAN_CHUNK (SCAN_T * SCAN_I)
#define NB_NODE ((N_VAR + SCAN_CHUNK - 1) / SCAN_CHUNK)   // 25
#define NB_CSTR ((N_CSTR + SCAN_CHUNK - 1) / SCAN_CHUNK)  // 13

__global__ void k_scan1_all() {
    int side = (blockIdx.x >= NB_NODE);
    int blk  = side ? blockIdx.x - NB_NODE : blockIdx.x;
    const int* in = side ? g_deg_cstr : g_deg_node;
    int* out = side ? g_row_cstr : g_row_node;
    int* bsum = side ? g_bsum_cstr : g_bsum_node;
    int n = side ? N_CSTR : N_VAR;
    __shared__ int sh[SCAN_T];
    int t = threadIdx.x;
    int base = blk * SCAN_CHUNK + t * SCAN_I;
    int loc[SCAN_I];
    int s = 0;
#pragma unroll
    for (int i = 0; i < SCAN_I; i++) {
        int idx = base + i;
        int v = (idx < n) ? in[idx] : 0;
        loc[i] = s; s += v;
    }
    sh[t] = s;
    __syncthreads();
    for (int off = 1; off < SCAN_T; off <<= 1) {
        int v = (t >= off) ? sh[t - off] : 0;
        __syncthreads();
        sh[t] += v;
        __syncthreads();
    }
    int pre = (t > 0) ? sh[t - 1] : 0;
#pragma unroll
    for (int i = 0; i < SCAN_I; i++) {
        int idx = base + i;
        if (idx < n) out[idx] = pre + loc[i];
    }
    if (t == SCAN_T - 1) bsum[blk] = sh[t];
}

__global__ void k_scan2() {
    int t = threadIdx.x;
    if (t == 0) {
        int s = 0;
        for (int i = 0; i < NB_NODE; i++) { int v = g_bsum_node[i]; g_bsum_node[i] = s; s += v; }
    }
    if (t == 1) {
        int s = 0;
        for (int i = 0; i < NB_CSTR; i++) { int v = g_bsum_cstr[i]; g_bsum_cstr[i] = s; s += v; }
    }
}

__global__ void k_scan3_all() {
    int side = (blockIdx.x >= NB_NODE);
    int blk  = side ? blockIdx.x - NB_NODE : blockIdx.x;
    int* row = side ? g_row_cstr : g_row_node;
    int* cur = side ? g_cur_cstr : g_cur_node;
    const int* bsum = side ? g_bsum_cstr : g_bsum_node;
    int n = side ? N_CSTR : N_VAR;
    int add = bsum[blk];
    int base = blk * SCAN_CHUNK;
    for (int i = threadIdx.x; i < SCAN_CHUNK; i += SCAN_T) {
        int idx = base + i;
        if (idx < n) { int v = row[idx] + add; row[idx] = v; cur[idx] = v; }
    }
}

// ---------------- scatter edges into CSR slots ----------------
__global__ void k_scatter(const int* __restrict__ src, const int* __restrict__ dst,
                          const float* __restrict__ attr) {
    for (int e = blockIdx.x * blockDim.x + threadIdx.x; e < NEDGE; e += gridDim.x * blockDim.x) {
        int s = src[e], d = dst[e];
        int a = __float_as_int(attr[e]);
        int p = atomicAdd(&g_cur_node[d], 1);
        g_e_node[p] = make_int2(s, a);
        int q = atomicAdd(&g_cur_cstr[s], 1);
        g_e_cstr[q] = make_int2(d, a);
    }
}

// ---------------- gather: warp/node, shfl broadcast, bf16 output ----------------
__global__ void k_gather_all() {
    int w = (blockIdx.x * blockDim.x + threadIdx.x) >> 5;
    int lane = threadIdx.x & 31;
    int side, node;
    if (w < N_VAR) { side = 0; node = w; }
    else { node = w - N_VAR; if (node >= N_CSTR) return; side = 1; }

    const int2* __restrict__ eb = side ? g_e_cstr : g_e_node;
    const int* __restrict__ row = side ? g_row_cstr : g_row_node;
    const int* __restrict__ deg = side ? g_deg_cstr : g_deg_node;
    const __nv_bfloat162* __restrict__ xs = side ? g_bf_node : g_bf_cstr;
    const float* __restrict__ sc = side ? g_scale_node : g_scale_cstr;
    const float* __restrict__ sf = side ? g_shift_node : g_shift_cstr;
    __nv_bfloat162* __restrict__ agg = side ? g_agg_cstr : g_agg_node;

    int beg = __ldg(&row[node]);
    int d = __ldg(&deg[node]);
    float2 acc = make_float2(0.f, 0.f);
    float sew = 0.f;

    for (int base = 0; base < d; base += 32) {
        int rem = d - base;
        int2 rec = make_int2(0, 0);
        if (lane < rem) rec = __ldg(&eb[beg + base + lane]);
        int m = min(rem, 32);
        for (int t = 0; t < m; t++) {
            int srcn = __shfl_sync(0xffffffffu, rec.x, t);
            float a = __int_as_float(__shfl_sync(0xffffffffu, rec.y, t));
            float2 xv = __bfloat1622float2(__ldg(&xs[(size_t)srcn * 32 + lane]));
            acc.x = fmaf(xv.x, a, acc.x);
            acc.y = fmaf(xv.y, a, acc.y);
            sew += a;
        }
    }
    float inv = 1.f / fmaxf((float)d, 1.f);
    float2 scl = ((const float2*)sc)[lane];
    float2 shf = ((const float2*)sf)[lane];
    float2 r;
    r.x = (scl.x * acc.x + shf.x * sew) * inv;
    r.y = (scl.y * acc.y + shf.y * sew) * inv;
    agg[(size_t)node * 32 + lane] = __float22bfloat162_rn(r);
}
#define GATHER_BLOCKS (((N_VAR + N_CSTR) * 32 + 255) / 256)

// ---------------- output: HMMA (mma.sync m16n8k16 bf16) + fp32 residual epilogue ----
// D[128x64] = A[128x128]_bf16 @ B[64x128]^T_bf16  (A=[agg|xn], B=[Wrel|Wroot], k-major)
// out = relu(D + bias + xn_fp32)
#define NOB_NODE ((N_VAR + 127) / 128)   // 782
#define NOB_CSTR ((N_CSTR + 127) / 128)  // 391
#define PADK 136                          // row stride in bf16 elems (272B: conflict-free)
#define SM_A_BYTES (128 * PADK * 2)       // 34816
#define SM_B_BYTES (64 * PADK * 2)        // 17408
#define HMMA_SMEM (SM_A_BYTES + SM_B_BYTES)

__global__ void __launch_bounds__(256) k_out_hmma(
        const float* __restrict__ nWrel, const float* __restrict__ nbrel,
        const float* __restrict__ nWroot, const float* __restrict__ nxraw,
        float* __restrict__ nout,
        const float* __restrict__ cWrel, const float* __restrict__ cbrel,
        const float* __restrict__ cWroot, const float* __restrict__ cxraw,
        float* __restrict__ cout) {
    int side = (blockIdx.x >= NOB_NODE);
    int blk  = side ? blockIdx.x - NOB_NODE : blockIdx.x;
    const float* __restrict__ Wrel  = side ? cWrel : nWrel;
    const float* __restrict__ brel  = side ? cbrel : nbrel;
    const float* __restrict__ Wroot = side ? cWroot : nWroot;
    const float* __restrict__ xr    = side ? cxraw : nxraw;
    float* __restrict__ outp = side ? cout : nout;
    const __nv_bfloat162* __restrict__ aggb = side ? g_agg_cstr : g_agg_node;
    const float* __restrict__ sc = side ? g_scale_cstr : g_scale_node;
    const float* __restrict__ sf = side ? g_shift_cstr : g_shift_node;
    int n = side ? N_CSTR : N_VAR;

    extern __shared__ __align__(16) char dynsm[];
    __nv_bfloat16* sA = (__nv_bfloat16*)dynsm;              // [128][PADK]
    __nv_bfloat16* sB = (__nv_bfloat16*)(dynsm + SM_A_BYTES); // [64][PADK]
    __shared__ float sBias[64], sSc[64], sSh[64];

    int tid = threadIdx.x;
    int base = blk * 128;

    if (tid < 64) {
        sBias[tid] = __ldg(&brel[tid]);
        sSc[tid] = __ldg(&sc[tid]);
        sSh[tid] = __ldg(&sf[tid]);
    }

    // ---- stage A: thread = (row m = tid>>1, half = tid&1) ----
    {
        int m = tid >> 1, half = tid & 1;
        int row = min(base + m, n - 1);
        if (half == 0) {
            const uint4* arow = (const uint4*)(aggb + (size_t)row * 32);
#pragma unroll
            for (int j = 0; j < 8; j++) {
                uint4 v = __ldg(&arow[j]);
                *(uint4*)(sA + m * PADK + j * 8) = v;
            }
        } else {
            const float4* xrow = (const float4*)(xr + (size_t)row * 64);
            const float4* sc4 = (const float4*)sc;
            const float4* sf4 = (const float4*)sf;
#pragma unroll
            for (int j = 0; j < 8; j++) {
                float4 x0 = __ldg(&xrow[2 * j]),  x1 = __ldg(&xrow[2 * j + 1]);
                float4 s0 = __ldg(&sc4[2 * j]),   s1 = __ldg(&sc4[2 * j + 1]);
                float4 h0 = __ldg(&sf4[2 * j]),   h1 = __ldg(&sf4[2 * j + 1]);
                uint4 v;
                v.x = pk2(fmaf(x0.x, s0.x, h0.x), fmaf(x0.y, s0.y, h0.y));
                v.y = pk2(fmaf(x0.z, s0.z, h0.z), fmaf(x0.w, s0.w, h0.w));
                v.z = pk2(fmaf(x1.x, s1.x, h1.x), fmaf(x1.y, s1.y, h1.y));
                v.w = pk2(fmaf(x1.z, s1.z, h1.z), fmaf(x1.w, s1.w, h1.w));
                *(uint4*)(sA + m * PADK + 64 + j * 8) = v;
            }
        }
    }
    // ---- stage B: tid<128: row nr = tid&63, which half = tid>>6 ----
    if (tid < 128) {
        int nr = tid & 63, which = tid >> 6;
        const float* Wsrc = which ? Wroot : Wrel;
        const float4* wrow = (const float4*)(Wsrc + nr * 64);
#pragma unroll
        for (int j = 0; j < 8; j++) {
            float4 a = __ldg(&wrow[2 * j]);
            float4 b = __ldg(&wrow[2 * j + 1]);
            uint4 v;
            v.x = pk2(a.x, a.y); v.y = pk2(a.z, a.w);
            v.z = pk2(b.x, b.y); v.w = pk2(b.z, b.w);
            *(uint4*)(sB + nr * PADK + which * 64 + j * 8) = v;
        }
    }
    __syncthreads();

    // ---- compute: warp w handles rows w*16 .. w*16+15 ----
    int w = tid >> 5, lane = tid & 31;
    int g = lane >> 2, tig = lane & 3;
    int mrow = w * 16 + g;

    float acc[8][4];
#pragma unroll
    for (int j = 0; j < 8; j++)
        acc[j][0] = acc[j][1] = acc[j][2] = acc[j][3] = 0.f;

    const u32* sAw = (const u32*)sA;
    const u32* sBw = (const u32*)sB;   // PADK even -> u32 indexing = (elem index)/2

#pragma unroll
    for (int kt = 0; kt < 8; kt++) {
        int k0 = kt * 16;
        u32 a0 = sAw[(mrow * PADK + k0 + 2 * tig) >> 1];
        u32 a1 = sAw[((mrow + 8) * PADK + k0 + 2 * tig) >> 1];
        u32 a2 = sAw[(mrow * PADK + k0 + 8 + 2 * tig) >> 1];
        u32 a3 = sAw[((mrow + 8) * PADK + k0 + 8 + 2 * tig) >> 1];
#pragma unroll
        for (int j = 0; j < 8; j++) {
            u32 b0 = sBw[((8 * j + g) * PADK + k0 + 2 * tig) >> 1];
            u32 b1 = sBw[((8 * j + g) * PADK + k0 + 8 + 2 * tig) >> 1];
            hmma16816(acc[j][0], acc[j][1], acc[j][2], acc[j][3], a0, a1, a2, a3, b0, b1);
        }
    }

    // ---- epilogue: out = relu(acc + bias + scale*x+shift), fp32 ----
    int r0 = base + w * 16 + g;
    int r1 = r0 + 8;
#pragma unroll
    for (int j = 0; j < 8; j++) {
        int c0 = 8 * j + 2 * tig;
        float bi0 = sBias[c0], bi1 = sBias[c0 + 1];
        float s0 = sSc[c0], s1 = sSc[c0 + 1];
        float h0 = sSh[c0], h1 = sSh[c0 + 1];
        if (r0 < n) {
            float2 x = *(const float2*)(xr + (size_t)r0 * 64 + c0);
            float2 o;
            o.x = fmaxf(acc[j][0] + bi0 + fmaf(x.x, s0, h0), 0.f);
            o.y = fmaxf(acc[j][1] + bi1 + fmaf(x.y, s1, h1), 0.f);
            *(float2*)(outp + (size_t)r0 * 64 + c0) = o;
        }
        if (r1 < n) {
            float2 x = *(const float2*)(xr + (size_t)r1 * 64 + c0);
            float2 o;
            o.x = fmaxf(acc[j][2] + bi0 + fmaf(x.x, s0, h0), 0.f);
            o.y = fmaxf(acc[j][3] + bi1 + fmaf(x.y, s1, h1), 0.f);
            *(float2*)(outp + (size_t)r1 * 64 + c0) = o;
        }
    }
}

// ---------------- launch ----------------
extern "C" void kernel_launch(void* const* d_in, const int* in_sizes, int n_in,
                              void* d_out, int out_size) {
    (void)in_sizes; (void)n_in; (void)out_size;
    const float* var_feats   = (const float*)d_in[0];
    const float* cstr_feats  = (const float*)d_in[1];
    const int*   edge_src    = (const int*)d_in[2];
    const int*   edge_dst    = (const int*)d_in[3];
    const float* edge_attr   = (const float*)d_in[4];
    const float* gn          = (const float*)d_in[5];
    const float* bn          = (const float*)d_in[6];
    const float* gc          = (const float*)d_in[7];
    const float* bc          = (const float*)d_in[8];
    const float* node_rel_w  = (const float*)d_in[9];
    const float* node_rel_b  = (const float*)d_in[10];
    const float* node_root_w = (const float*)d_in[11];
    const float* cstr_rel_w  = (const float*)d_in[12];
    const float* cstr_rel_b  = (const float*)d_in[13];
    const float* cstr_root_w = (const float*)d_in[14];

    float* out_node = (float*)d_out;
    float* out_cstr = out_node + (size_t)N_VAR * D;

    cudaFuncSetAttribute(k_out_hmma, cudaFuncAttributeMaxDynamicSharedMemorySize, HMMA_SMEM);

    // slot 4 (ncu's captured launch) = k_bnstats(var) — next unknown
    k_zero_deg<<<391, 256>>>();
    k_zero_stats<<<1, 128>>>();
    k_hist<<<2048, 256>>>(edge_src, edge_dst);
    k_bnstats<<<296, dim3(64, 4)>>>(var_feats, N_VAR, 0);     // <- profiled
    k_bnstats<<<296, dim3(64, 4)>>>(cstr_feats, N_CSTR, 1);
    k_finstats<<<1, 128>>>(gn, bn, gc, bc);
    k_scan1_all<<<NB_NODE + NB_CSTR, SCAN_T>>>();
    k_scan2<<<1, 2>>>();
    k_scan3_all<<<NB_NODE + NB_CSTR, SCAN_T>>>();
    k_scatter<<<2048, 256>>>(edge_src, edge_dst, edge_attr);
    k_gather_all<<<GATHER_BLOCKS, 256>>>();
    k_out_hmma<<<NOB_NODE + NOB_CSTR, 256, HMMA_SMEM>>>(
        node_rel_w, node_rel_b, node_root_w, var_feats, out_node,
        cstr_rel_w, cstr_rel_b, cstr_root_w, cstr_feats, out_cstr);
}

// round 10
// speedup vs baseline: 1.7772x; 1.0090x over previous
#include <cuda_runtime.h>
#include <cuda_bf16.h>

#define N_VAR  100000
#define N_CSTR 50000
#define NEDGE  1000000
#define D      64
#define BN_EPS 1e-5f

typedef unsigned long long u64;
typedef unsigned int u32;

// ---------------- scratch ----------------
__device__ __nv_bfloat162 g_bf_node[N_VAR * 32];
__device__ __nv_bfloat162 g_bf_cstr[N_CSTR * 32];
__device__ __nv_bfloat162 g_agg_node[N_VAR * 32];   // mean-aggregated messages, bf16
__device__ __nv_bfloat162 g_agg_cstr[N_CSTR * 32];
__device__ int2  g_e_node[NEDGE];
__device__ int2  g_e_cstr[NEDGE];
__device__ int   g_deg_node[N_VAR];
__device__ int   g_deg_cstr[N_CSTR];
__device__ int   g_row_node[N_VAR];
__device__ int   g_row_cstr[N_CSTR];
__device__ int   g_cur_node[N_VAR];
__device__ int   g_cur_cstr[N_CSTR];
__device__ float g_stats_node[2 * D];
__device__ float g_stats_cstr[2 * D];
__device__ float g_scale_node[D], g_shift_node[D];
__device__ float g_scale_cstr[D], g_shift_cstr[D];
__device__ int   g_bsum_node[32];
__device__ int   g_bsum_cstr[32];

// ---------------- helpers ----------------
__device__ __forceinline__ u32 pk2(float lo, float hi) {
    u32 r;
    asm("cvt.rn.bf16x2.f32 %0, %1, %2;" : "=r"(r) : "f"(hi), "f"(lo));
    return r;
}
__device__ __forceinline__ void hmma16816(float& d0, float& d1, float& d2, float& d3,
                                          u32 a0, u32 a1, u32 a2, u32 a3,
                                          u32 b0, u32 b1) {
    asm volatile(
        "mma.sync.aligned.m16n8k16.row.col.f32.bf16.bf16.f32 "
        "{%0,%1,%2,%3}, {%4,%5,%6,%7}, {%8,%9}, {%0,%1,%2,%3};"
        : "+f"(d0), "+f"(d1), "+f"(d2), "+f"(d3)
        : "r"(a0), "r"(a1), "r"(a2), "r"(a3), "r"(b0), "r"(b1));
}

// ---------------- zero kernels ----------------
__global__ void k_zero_deg() {
    int i = blockIdx.x * blockDim.x + threadIdx.x;
    int stride = gridDim.x * blockDim.x;
    for (int j = i; j < N_VAR; j += stride) g_deg_node[j] = 0;
    for (int j = i; j < N_CSTR; j += stride) g_deg_cstr[j] = 0;
}
__global__ void k_zero_stats() {
    int i = threadIdx.x;
    if (i < 2 * D) { g_stats_node[i] = 0.f; g_stats_cstr[i] = 0.f; }
}

// ---------------- BN stats + bf16 conversion ----------------
__global__ void k_bnstats(const float* __restrict__ x, int n, int which) {
    float* stats = which ? g_stats_cstr : g_stats_node;
    __nv_bfloat16* bf = (__nv_bfloat16*)(which ? g_bf_cstr : g_bf_node);
    int c = threadIdx.x;
    int step = gridDim.x * blockDim.y;
    float s = 0.f, q = 0.f;
    for (int r = blockIdx.x * blockDim.y + threadIdx.y; r < n; r += step) {
        float v = x[(size_t)r * D + c];
        bf[(size_t)r * D + c] = __float2bfloat16_rn(v);
        s += v; q = fmaf(v, v, q);
    }
    __shared__ float shs[4][64], shq[4][64];
    shs[threadIdx.y][c] = s; shq[threadIdx.y][c] = q;
    __syncthreads();
    if (threadIdx.y == 0) {
        float S = shs[0][c] + shs[1][c] + shs[2][c] + shs[3][c];
        float Q = shq[0][c] + shq[1][c] + shq[2][c] + shq[3][c];
        atomicAdd(&stats[c], S);
        atomicAdd(&stats[D + c], Q);
    }
}

// ---------------- finalize BN scale/shift ----------------
__global__ void k_finstats(const float* __restrict__ gn, const float* __restrict__ bn,
                           const float* __restrict__ gc, const float* __restrict__ bc) {
    int c = threadIdx.x;
    if (c < D) {
        float m = g_stats_node[c] / (float)N_VAR;
        float v = g_stats_node[D + c] / (float)N_VAR - m * m;
        float sc = gn[c] * rsqrtf(v + BN_EPS);
        g_scale_node[c] = sc;
        g_shift_node[c] = fmaf(-m, sc, bn[c]);
    } else if (c < 2 * D) {
        int cc = c - D;
        float m = g_stats_cstr[cc] / (float)N_CSTR;
        float v = g_stats_cstr[D + cc] / (float)N_CSTR - m * m;
        float sc = gc[cc] * rsqrtf(v + BN_EPS);
        g_scale_cstr[cc] = sc;
        g_shift_cstr[cc] = fmaf(-m, sc, bc[cc]);
    }
}

// ---------------- degree histogram ----------------
__global__ void k_hist(const int* __restrict__ src, const int* __restrict__ dst) {
    for (int e = blockIdx.x * blockDim.x + threadIdx.x; e < NEDGE; e += gridDim.x * blockDim.x) {
        atomicAdd(&g_deg_node[dst[e]], 1);
        atomicAdd(&g_deg_cstr[src[e]], 1);
    }
}

// ---------------- scans ----------------
#define SCAN_T 256
#define SCAN_I 16
#define SCAN_CHUNK (SCAN_T * SCAN_I)
#define NB_NODE ((N_VAR + SCAN_CHUNK - 1) / SCAN_CHUNK)   // 25
#define NB_CSTR ((N_CSTR + SCAN_CHUNK - 1) / SCAN_CHUNK)  // 13

__global__ void k_scan1_all() {
    int side = (blockIdx.x >= NB_NODE);
    int blk  = side ? blockIdx.x - NB_NODE : blockIdx.x;
    const int* in = side ? g_deg_cstr : g_deg_node;
    int* out = side ? g_row_cstr : g_row_node;
    int* bsum = side ? g_bsum_cstr : g_bsum_node;
    int n = side ? N_CSTR : N_VAR;
    __shared__ int sh[SCAN_T];
    int t = threadIdx.x;
    int base = blk * SCAN_CHUNK + t * SCAN_I;
    int loc[SCAN_I];
    int s = 0;
#pragma unroll
    for (int i = 0; i < SCAN_I; i++) {
        int idx = base + i;
        int v = (idx < n) ? in[idx] : 0;
        loc[i] = s; s += v;
    }
    sh[t] = s;
    __syncthreads();
    for (int off = 1; off < SCAN_T; off <<= 1) {
        int v = (t >= off) ? sh[t - off] : 0;
        __syncthreads();
        sh[t] += v;
        __syncthreads();
    }
    int pre = (t > 0) ? sh[t - 1] : 0;
#pragma unroll
    for (int i = 0; i < SCAN_I; i++) {
        int idx = base + i;
        if (idx < n) out[idx] = pre + loc[i];
    }
    if (t == SCAN_T - 1) bsum[blk] = sh[t];
}

__global__ void k_scan2() {
    int t = threadIdx.x;
    if (t == 0) {
        int s = 0;
        for (int i = 0; i < NB_NODE; i++) { int v = g_bsum_node[i]; g_bsum_node[i] = s; s += v; }
    }
    if (t == 1) {
        int s = 0;
        for (int i = 0; i < NB_CSTR; i++) { int v = g_bsum_cstr[i]; g_bsum_cstr[i] = s; s += v; }
    }
}

__global__ void k_scan3_all() {
    int side = (blockIdx.x >= NB_NODE);
    int blk  = side ? blockIdx.x - NB_NODE : blockIdx.x;
    int* row = side ? g_row_cstr : g_row_node;
    int* cur = side ? g_cur_cstr : g_cur_node;
    const int* bsum = side ? g_bsum_cstr : g_bsum_node;
    int n = side ? N_CSTR : N_VAR;
    int add = bsum[blk];
    int base = blk * SCAN_CHUNK;
    for (int i = threadIdx.x; i < SCAN_CHUNK; i += SCAN_T) {
        int idx = base + i;
        if (idx < n) { int v = row[idx] + add; row[idx] = v; cur[idx] = v; }
    }
}

// ---------------- scatter edges into CSR slots ----------------
__global__ void k_scatter(const int* __restrict__ src, const int* __restrict__ dst,
                          const float* __restrict__ attr) {
    for (int e = blockIdx.x * blockDim.x + threadIdx.x; e < NEDGE; e += gridDim.x * blockDim.x) {
        int s = src[e], d = dst[e];
        int a = __float_as_int(attr[e]);
        int p = atomicAdd(&g_cur_node[d], 1);
        g_e_node[p] = make_int2(s, a);
        int q = atomicAdd(&g_cur_cstr[s], 1);
        g_e_cstr[q] = make_int2(d, a);
    }
}

// ---------------- gather: warp/node, shfl broadcast, bf16 output ----------------
__global__ void k_gather_all() {
    int w = (blockIdx.x * blockDim.x + threadIdx.x) >> 5;
    int lane = threadIdx.x & 31;
    int side, node;
    if (w < N_VAR) { side = 0; node = w; }
    else { node = w - N_VAR; if (node >= N_CSTR) return; side = 1; }

    const int2* __restrict__ eb = side ? g_e_cstr : g_e_node;
    const int* __restrict__ row = side ? g_row_cstr : g_row_node;
    const int* __restrict__ deg = side ? g_deg_cstr : g_deg_node;
    const __nv_bfloat162* __restrict__ xs = side ? g_bf_node : g_bf_cstr;
    const float* __restrict__ sc = side ? g_scale_node : g_scale_cstr;
    const float* __restrict__ sf = side ? g_shift_node : g_shift_cstr;
    __nv_bfloat162* __restrict__ agg = side ? g_agg_cstr : g_agg_node;

    int beg = __ldg(&row[node]);
    int d = __ldg(&deg[node]);
    float2 acc = make_float2(0.f, 0.f);
    float sew = 0.f;

    for (int base = 0; base < d; base += 32) {
        int rem = d - base;
        int2 rec = make_int2(0, 0);
        if (lane < rem) rec = __ldg(&eb[beg + base + lane]);
        int m = min(rem, 32);
        for (int t = 0; t < m; t++) {
            int srcn = __shfl_sync(0xffffffffu, rec.x, t);
            float a = __int_as_float(__shfl_sync(0xffffffffu, rec.y, t));
            float2 xv = __bfloat1622float2(__ldg(&xs[(size_t)srcn * 32 + lane]));
            acc.x = fmaf(xv.x, a, acc.x);
            acc.y = fmaf(xv.y, a, acc.y);
            sew += a;
        }
    }
    float inv = 1.f / fmaxf((float)d, 1.f);
    float2 scl = ((const float2*)sc)[lane];
    float2 shf = ((const float2*)sf)[lane];
    float2 r;
    r.x = (scl.x * acc.x + shf.x * sew) * inv;
    r.y = (scl.y * acc.y + shf.y * sew) * inv;
    agg[(size_t)node * 32 + lane] = __float22bfloat162_rn(r);
}
#define GATHER_BLOCKS (((N_VAR + N_CSTR) * 32 + 255) / 256)

// ---------------- output: HMMA bf16 split-K GEMM + fp32 residual epilogue ----------
// D[128x64] = A[128x192]_bf16 @ B[64x192]^T_bf16
//   A = [agg(64) | hi(xn)(64) | lo(xn)(64)],  B = [Wrel | Wroot | Wroot]
//   xn = scale*x+shift (fp32), hi = bf16(xn), lo = bf16(xn - hi)  -> fp32-grade root term
// out = relu(D + bias + xn_fp32)
#define NOB_NODE ((N_VAR + 127) / 128)   // 782
#define NOB_CSTR ((N_CSTR + 127) / 128)  // 391
#define KDIM 192
#define PADK 200                          // row stride elems (400B ≡ 4 words mod 32: conflict-free)
#define SM_A_BYTES (128 * PADK * 2)       // 51200
#define SM_B_BYTES (64 * PADK * 2)        // 25600
#define HMMA_SMEM (SM_A_BYTES + SM_B_BYTES)

__global__ void __launch_bounds__(256) k_out_hmma(
        const float* __restrict__ nWrel, const float* __restrict__ nbrel,
        const float* __restrict__ nWroot, const float* __restrict__ nxraw,
        float* __restrict__ nout,
        const float* __restrict__ cWrel, const float* __restrict__ cbrel,
        const float* __restrict__ cWroot, const float* __restrict__ cxraw,
        float* __restrict__ cout) {
    int side = (blockIdx.x >= NOB_NODE);
    int blk  = side ? blockIdx.x - NOB_NODE : blockIdx.x;
    const float* __restrict__ Wrel  = side ? cWrel : nWrel;
    const float* __restrict__ brel  = side ? cbrel : nbrel;
    const float* __restrict__ Wroot = side ? cWroot : nWroot;
    const float* __restrict__ xr    = side ? cxraw : nxraw;
    float* __restrict__ outp = side ? cout : nout;
    const __nv_bfloat162* __restrict__ aggb = side ? g_agg_cstr : g_agg_node;
    const float* __restrict__ sc = side ? g_scale_cstr : g_scale_node;
    const float* __restrict__ sf = side ? g_shift_cstr : g_shift_node;
    int n = side ? N_CSTR : N_VAR;

    extern __shared__ __align__(16) char dynsm[];
    __nv_bfloat16* sA = (__nv_bfloat16*)dynsm;                 // [128][PADK]
    __nv_bfloat16* sB = (__nv_bfloat16*)(dynsm + SM_A_BYTES);  // [64][PADK]
    __shared__ float sBias[64], sSc[64], sSh[64];

    int tid = threadIdx.x;
    int base = blk * 128;

    if (tid < 64) {
        sBias[tid] = __ldg(&brel[tid]);
        sSc[tid] = __ldg(&sc[tid]);
        sSh[tid] = __ldg(&sf[tid]);
    }

    // ---- stage A: thread = (row m = tid>>1, half h = tid&1), h covers cols [32h,32h+32) ----
    {
        int m = tid >> 1, h = tid & 1;
        int row = min(base + m, n - 1);
        // agg: 4 uint4 (32 bf16)
        const uint4* arow = (const uint4*)(aggb + (size_t)row * 32);
#pragma unroll
        for (int j = 0; j < 4; j++) {
            uint4 v = __ldg(&arow[h * 4 + j]);
            *(uint4*)(sA + m * PADK + h * 32 + j * 8) = v;
        }
        // xn hi/lo: 32 floats -> 32 hi bf16 + 32 lo bf16
        const float4* xrow = (const float4*)(xr + (size_t)row * 64 + h * 32);
        const float4* sc4 = (const float4*)(sc + h * 32);
        const float4* sf4 = (const float4*)(sf + h * 32);
#pragma unroll
        for (int j = 0; j < 4; j++) {
            float4 x0 = __ldg(&xrow[2 * j]),  x1 = __ldg(&xrow[2 * j + 1]);
            float4 s0 = __ldg(&sc4[2 * j]),   s1 = __ldg(&sc4[2 * j + 1]);
            float4 h0 = __ldg(&sf4[2 * j]),   h1 = __ldg(&sf4[2 * j + 1]);
            float xn[8];
            xn[0] = fmaf(x0.x, s0.x, h0.x); xn[1] = fmaf(x0.y, s0.y, h0.y);
            xn[2] = fmaf(x0.z, s0.z, h0.z); xn[3] = fmaf(x0.w, s0.w, h0.w);
            xn[4] = fmaf(x1.x, s1.x, h1.x); xn[5] = fmaf(x1.y, s1.y, h1.y);
            xn[6] = fmaf(x1.z, s1.z, h1.z); xn[7] = fmaf(x1.w, s1.w, h1.w);
            uint4 vh, vl;
            u32* ph = (u32*)&vh; u32* pl = (u32*)&vl;
#pragma unroll
            for (int q = 0; q < 4; q++) {
                float a = xn[2 * q], b = xn[2 * q + 1];
                __nv_bfloat16 ha = __float2bfloat16_rn(a);
                __nv_bfloat16 hb = __float2bfloat16_rn(b);
                float fa = __bfloat162float(ha), fb = __bfloat162float(hb);
                ph[q] = pk2(a, b);                    // hi pair (rn of a,b)
                pl[q] = pk2(a - fa, b - fb);          // lo pair
            }
            *(uint4*)(sA + m * PADK + 64 + h * 32 + j * 8) = vh;
            *(uint4*)(sA + m * PADK + 128 + h * 32 + j * 8) = vl;
        }
    }
    // ---- stage B: tid<192: nr = tid%64, seg = tid/64 (0:Wrel,1:Wroot,2:Wroot) ----
    if (tid < 192) {
        int nr = tid & 63, seg = tid >> 6;
        const float* Wsrc = seg ? Wroot : Wrel;
        const float4* wrow = (const float4*)(Wsrc + nr * 64);
#pragma unroll
        for (int j = 0; j < 8; j++) {
            float4 a = __ldg(&wrow[2 * j]);
            float4 b = __ldg(&wrow[2 * j + 1]);
            uint4 v;
            v.x = pk2(a.x, a.y); v.y = pk2(a.z, a.w);
            v.z = pk2(b.x, b.y); v.w = pk2(b.z, b.w);
            *(uint4*)(sB + nr * PADK + seg * 64 + j * 8) = v;
        }
    }
    __syncthreads();

    // ---- compute: warp w handles rows w*16 .. w*16+15, all 64 cols ----
    int w = tid >> 5, lane = tid & 31;
    int g = lane >> 2, tig = lane & 3;
    int mrow = w * 16 + g;

    float acc[8][4];
#pragma unroll
    for (int j = 0; j < 8; j++)
        acc[j][0] = acc[j][1] = acc[j][2] = acc[j][3] = 0.f;

    const u32* sAw = (const u32*)sA;
    const u32* sBw = (const u32*)sB;

#pragma unroll
    for (int kt = 0; kt < KDIM / 16; kt++) {
        int k0 = kt * 16;
        u32 a0 = sAw[(mrow * PADK + k0 + 2 * tig) >> 1];
        u32 a1 = sAw[((mrow + 8) * PADK + k0 + 2 * tig) >> 1];
        u32 a2 = sAw[(mrow * PADK + k0 + 8 + 2 * tig) >> 1];
        u32 a3 = sAw[((mrow + 8) * PADK + k0 + 8 + 2 * tig) >> 1];
#pragma unroll
        for (int j = 0; j < 8; j++) {
            u32 b0 = sBw[((8 * j + g) * PADK + k0 + 2 * tig) >> 1];
            u32 b1 = sBw[((8 * j + g) * PADK + k0 + 8 + 2 * tig) >> 1];
            hmma16816(acc[j][0], acc[j][1], acc[j][2], acc[j][3], a0, a1, a2, a3, b0, b1);
        }
    }

    // ---- epilogue: out = relu(acc + bias + scale*x+shift), fp32 ----
    int r0 = base + w * 16 + g;
    int r1 = r0 + 8;
#pragma unroll
    for (int j = 0; j < 8; j++) {
        int c0 = 8 * j + 2 * tig;
        float bi0 = sBias[c0], bi1 = sBias[c0 + 1];
        float s0 = sSc[c0], s1 = sSc[c0 + 1];
        float h0 = sSh[c0], h1 = sSh[c0 + 1];
        if (r0 < n) {
            float2 x = *(const float2*)(xr + (size_t)r0 * 64 + c0);
            float2 o;
            o.x = fmaxf(acc[j][0] + bi0 + fmaf(x.x, s0, h0), 0.f);
            o.y = fmaxf(acc[j][1] + bi1 + fmaf(x.y, s1, h1), 0.f);
            *(float2*)(outp + (size_t)r0 * 64 + c0) = o;
        }
        if (r1 < n) {
            float2 x = *(const float2*)(xr + (size_t)r1 * 64 + c0);
            float2 o;
            o.x = fmaxf(acc[j][2] + bi0 + fmaf(x.x, s0, h0), 0.f);
            o.y = fmaxf(acc[j][3] + bi1 + fmaf(x.y, s1, h1), 0.f);
            *(float2*)(outp + (size_t)r1 * 64 + c0) = o;
        }
    }
}

// ---------------- launch ----------------
extern "C" void kernel_launch(void* const* d_in, const int* in_sizes, int n_in,
                              void* d_out, int out_size) {
    (void)in_sizes; (void)n_in; (void)out_size;
    const float* var_feats   = (const float*)d_in[0];
    const float* cstr_feats  = (const float*)d_in[1];
    const int*   edge_src    = (const int*)d_in[2];
    const int*   edge_dst    = (const int*)d_in[3];
    const float* edge_attr   = (const float*)d_in[4];
    const float* gn          = (const float*)d_in[5];
    const float* bn          = (const float*)d_in[6];
    const float* gc          = (const float*)d_in[7];
    const float* bc          = (const float*)d_in[8];
    const float* node_rel_w  = (const float*)d_in[9];
    const float* node_rel_b  = (const float*)d_in[10];
    const float* node_root_w = (const float*)d_in[11];
    const float* cstr_rel_w  = (const float*)d_in[12];
    const float* cstr_rel_b  = (const float*)d_in[13];
    const float* cstr_root_w = (const float*)d_in[14];

    float* out_node = (float*)d_out;
    float* out_cstr = out_node + (size_t)N_VAR * D;

    cudaFuncSetAttribute(k_out_hmma, cudaFuncAttributeMaxDynamicSharedMemorySize, HMMA_SMEM);

    // slot 4 (ncu's captured launch) = k_bnstats(var) — verifies the grid bump
    k_zero_deg<<<391, 256>>>();
    k_zero_stats<<<1, 128>>>();
    k_hist<<<2048, 256>>>(edge_src, edge_dst);
    k_bnstats<<<888, dim3(64, 4)>>>(var_feats, N_VAR, 0);     // <- profiled
    k_bnstats<<<888, dim3(64, 4)>>>(cstr_feats, N_CSTR, 1);
    k_finstats<<<1, 128>>>(gn, bn, gc, bc);
    k_scan1_all<<<NB_NODE + NB_CSTR, SCAN_T>>>();
    k_scan2<<<1, 2>>>();
    k_scan3_all<<<NB_NODE + NB_CSTR, SCAN_T>>>();
    k_scatter<<<2048, 256>>>(edge_src, edge_dst, edge_attr);
    k_gather_all<<<GATHER_BLOCKS, 256>>>();
    k_out_hmma<<<NOB_NODE + NOB_CSTR, 256, HMMA_SMEM>>>(
        node_rel_w, node_rel_b, node_root_w, var_feats, out_node,
        cstr_rel_w, cstr_rel_b, cstr_root_w, cstr_feats, out_cstr);
}